// round 9
// baseline (speedup 1.0000x reference)
#include <cuda_runtime.h>
#include <cuda_fp16.h>
#include <math.h>
#include <stdint.h>

// ---------------------------------------------------------------------------
// Problem constants
// ---------------------------------------------------------------------------
#define B_  4
#define L_  384
#define H_  128
#define F_  384
#define M1_ (B_ * L_ * L_)      // 589824 edge rows

// ---------------------------------------------------------------------------
// Device scratch (allocation-free rule)
// ---------------------------------------------------------------------------
__device__ __half g_hEh[(size_t)M1_ * H_];      // fp16 copy of h_E
__device__ __half g_T1h[(size_t)M1_ * F_];      // fp16 gelu(h_E @ fw1 + fb1)
__device__ float  g_xconv[(size_t)B_ * L_ * F_];
__device__ float  g_predm[B_ * L_];
__device__ __half g_fw1T[F_ * H_];              // [n=384][k=128] fp16
__device__ __half g_fw2T[F_ * F_];              // [n=384][k=384] fp16

__device__ __forceinline__ float gelu_f(float x) {
    return 0.5f * x * (1.0f + erff(x * 0.70710678118654752440f));
}

__device__ __forceinline__ uint32_t smem_u32(const void* p) {
    uint32_t a;
    asm("{ .reg .u64 t; cvta.to.shared.u64 t, %1; cvt.u32.u64 %0, t; }" : "=r"(a) : "l"(p));
    return a;
}

// m16n8k16 fp16 MMA, fp32 accumulate.
__device__ __forceinline__ void mma16(float* c, const uint32_t* a, uint32_t b0, uint32_t b1) {
    asm volatile(
        "mma.sync.aligned.m16n8k16.row.col.f32.f16.f16.f32 "
        "{%0,%1,%2,%3}, {%4,%5,%6,%7}, {%8,%9}, {%0,%1,%2,%3};"
        : "+f"(c[0]), "+f"(c[1]), "+f"(c[2]), "+f"(c[3])
        : "r"(a[0]), "r"(a[1]), "r"(a[2]), "r"(a[3]), "r"(b0), "r"(b1));
}

// ldmatrix x4: four 8x8 b16 matrices, per-lane row addresses.
__device__ __forceinline__ void ldsm4(uint32_t& r0, uint32_t& r1, uint32_t& r2,
                                      uint32_t& r3, uint32_t addr) {
    asm volatile("ldmatrix.sync.aligned.m8n8.x4.shared.b16 {%0,%1,%2,%3}, [%4];"
                 : "=r"(r0), "=r"(r1), "=r"(r2), "=r"(r3) : "r"(addr));
}

#define CP_COMMIT() asm volatile("cp.async.commit_group;" ::: "memory")
#define CP_WAIT1()  asm volatile("cp.async.wait_group 1;" ::: "memory")
#define CP_WAIT0()  asm volatile("cp.async.wait_group 0;" ::: "memory")

// Async-stage a [128 rows x 32 half] block (gmem row stride ldg halves) into
// smem with row pitch 40 halves (80 B). 256 threads x 2 x 16B.
__device__ __forceinline__ void stage_async_h(const __half* __restrict__ g, int ldg,
                                              uint32_t s_addr, int tid) {
#pragma unroll
    for (int i = 0; i < 2; ++i) {
        int idx = tid + i * 256;            // 0..511
        int row = idx >> 2, q = idx & 3;    // 4 x 16B per 64B row
        uint32_t dst = s_addr + (uint32_t)(row * 80 + q * 16);
        const __half* src = g + (size_t)row * ldg + q * 8;
        asm volatile("cp.async.cg.shared.global [%0], [%1], 16;" :: "r"(dst), "l"(src));
    }
}

// ---------------------------------------------------------------------------
// Dynamic smem layout (bytes)
// ---------------------------------------------------------------------------
#define SB_   10240                 // one 128x40-half buffer
#define O_A   0                     // 2 buffers
#define O_B   (2 * SB_)             // 2 buffers
#define O_BIAS (4 * SB_)            // 512 B
#define O_RED  (O_BIAS + 512)       // 2048 B (gemm2)
#define O_XACC (O_RED + 2048)       // 512 B  (gemm2)
#define SMEM1  (O_BIAS + 512)
#define SMEM2  (O_XACC + 512)

// ---------------------------------------------------------------------------
// Kernel 0a: convert h_E (fp32) -> fp16
// ---------------------------------------------------------------------------
__global__ void __launch_bounds__(256) conv_hE(const float* __restrict__ hE) {
    size_t i = ((size_t)blockIdx.x * 256 + threadIdx.x) * 4;
    float4 v = *reinterpret_cast<const float4*>(hE + i);
    *reinterpret_cast<__half2*>(g_hEh + i)     = __floats2half2_rn(v.x, v.y);
    *reinterpret_cast<__half2*>(g_hEh + i + 2) = __floats2half2_rn(v.z, v.w);
}

// ---------------------------------------------------------------------------
// Kernel 0b: transpose weights to [n][k] fp16
// ---------------------------------------------------------------------------
__global__ void __launch_bounds__(256) transpose_w(const float* __restrict__ fw1,
                                                   const float* __restrict__ fw2) {
    int idx = blockIdx.x * 256 + threadIdx.x;
    if (idx < F_ * H_) {
        int n = idx / H_, k = idx % H_;
        g_fw1T[idx] = __float2half_rn(fw1[k * F_ + n]);
    }
    int i2 = idx - F_ * H_;
    if (i2 >= 0 && i2 < F_ * F_) {
        int n = i2 / F_, k = i2 % F_;
        g_fw2T[i2] = __float2half_rn(fw2[k * F_ + n]);
    }
}

// ---------------------------------------------------------------------------
// Warp-level MMA over one staged K=32 chunk (2 x K=16 steps), ldmatrix feed.
// aA/aB: smem byte addresses of the staged buffers.
// aoffA/aoffB: per-lane ldmatrix address offsets (precomputed).
//   A x4 @ (mt,ks): matrices (m0-7,kk)(m8-15,kk)(m0-7,kk+8)(m8-15,kk+8)
//   B x4 @ nt:      matrices (n,k0-7)(n,k8-15)(n,k16-23)(n,k24-31)
// ---------------------------------------------------------------------------
__device__ __forceinline__ void mma_chunk(uint32_t aA, uint32_t aB,
                                          float acc[2][8][4],
                                          uint32_t aoffA, uint32_t aoffB) {
    uint32_t bf[8][4];
#pragma unroll
    for (int nt = 0; nt < 8; ++nt)
        ldsm4(bf[nt][0], bf[nt][1], bf[nt][2], bf[nt][3], aB + aoffB + nt * 640);

    uint32_t af[2][2][4];
#pragma unroll
    for (int mt = 0; mt < 2; ++mt)
#pragma unroll
        for (int ks = 0; ks < 2; ++ks)
            ldsm4(af[mt][ks][0], af[mt][ks][1], af[mt][ks][2], af[mt][ks][3],
                  aA + aoffA + mt * 1280 + ks * 32);

#pragma unroll
    for (int ks = 0; ks < 2; ++ks)
#pragma unroll
        for (int mt = 0; mt < 2; ++mt)
#pragma unroll
            for (int nt = 0; nt < 8; ++nt)
                mma16(acc[mt][nt], af[mt][ks], bf[nt][ks * 2], bf[nt][ks * 2 + 1]);
}

// ---------------------------------------------------------------------------
// Kernel 1: T1 = fp16(gelu(h_E @ fw1 + fb1))
//   grid (3, 4608). CTA tile 128x128, warp tile 32x64, K=128 in 4 chunks,
//   cp.async double-buffered, ldmatrix fragment feed.
// ---------------------------------------------------------------------------
__global__ void __launch_bounds__(256, 2) gemm1_mma(const float* __restrict__ fb1) {
    extern __shared__ char smc[];
    const uint32_t sb = smem_u32(smc);
    float* biasS = reinterpret_cast<float*>(smc + O_BIAS);

    const int tid = threadIdx.x;
    const int wid = tid >> 5, lane = tid & 31;
    const int gid = lane >> 2, tig = lane & 3;
    const int g8 = lane >> 3, lr = lane & 7;
    const int wm = wid & 3, wn = wid >> 2;
    const int m0 = blockIdx.y * 128, n0 = blockIdx.x * 128;

    const uint32_t aoffA = (uint32_t)((wm * 32 + (g8 & 1) * 8 + lr) * 80 + (g8 >> 1) * 16);
    const uint32_t aoffB = (uint32_t)((wn * 64 + lr) * 80 + g8 * 16);

    if (tid < 128) biasS[tid] = fb1[n0 + tid];

    float acc[2][8][4];
#pragma unroll
    for (int mt = 0; mt < 2; ++mt)
#pragma unroll
        for (int nt = 0; nt < 8; ++nt)
#pragma unroll
            for (int j = 0; j < 4; ++j) acc[mt][nt][j] = 0.f;

    const __half* Abase = g_hEh + (size_t)m0 * H_;
    const __half* Bbase = g_fw1T + (size_t)n0 * H_;

    stage_async_h(Abase, H_, sb + O_A, tid);
    stage_async_h(Bbase, H_, sb + O_B, tid);
    CP_COMMIT();

    for (int kc = 0; kc < 4; ++kc) {
        const int cur = kc & 1;
        if (kc + 1 < 4) {
            stage_async_h(Abase + (kc + 1) * 32, H_, sb + O_A + (1 - cur) * SB_, tid);
            stage_async_h(Bbase + (kc + 1) * 32, H_, sb + O_B + (1 - cur) * SB_, tid);
            CP_COMMIT();
            CP_WAIT1();
        } else {
            CP_WAIT0();
        }
        __syncthreads();
        mma_chunk(sb + O_A + cur * SB_, sb + O_B + cur * SB_, acc, aoffA, aoffB);
        __syncthreads();
    }

    // Epilogue: bias + exact-erf gelu (fp32), store fp16 half2
#pragma unroll
    for (int mt = 0; mt < 2; ++mt)
#pragma unroll
        for (int nt = 0; nt < 8; ++nt) {
            float* c = acc[mt][nt];
            int lrr = wm * 32 + mt * 16 + gid;
            int lc = wn * 64 + nt * 8 + 2 * tig;
            float b0v = biasS[lc], b1v = biasS[lc + 1];
            size_t base = (size_t)(m0 + lrr) * F_ + n0 + lc;
            *reinterpret_cast<__half2*>(g_T1h + base) =
                __floats2half2_rn(gelu_f(c[0] + b0v), gelu_f(c[1] + b1v));
            *reinterpret_cast<__half2*>(g_T1h + base + (size_t)8 * F_) =
                __floats2half2_rn(gelu_f(c[2] + b0v), gelu_f(c[3] + b1v));
        }
}

// ---------------------------------------------------------------------------
// Kernel 2: per (bl, n-tile): T2 = gelu(T1_bl @ fw2 + fb2);
//           xconv[bl, n] = sum_k hV[b,k,n] * T2[k,n]   (T2 never hits memory)
//   grid (3, 1536). 3 m-tiles of 128 k-edges, K=384 in 12 chunks, ldmatrix.
// ---------------------------------------------------------------------------
__global__ void __launch_bounds__(256, 2) gemm2_mma(const float* __restrict__ hV,
                                                    const float* __restrict__ fb2) {
    extern __shared__ char smc[];
    const uint32_t sb = smem_u32(smc);
    float* biasS = reinterpret_cast<float*>(smc + O_BIAS);
    float (*red)[128] = reinterpret_cast<float (*)[128]>(smc + O_RED);
    float* xacc = reinterpret_cast<float*>(smc + O_XACC);

    const int tid = threadIdx.x;
    const int wid = tid >> 5, lane = tid & 31;
    const int gid = lane >> 2, tig = lane & 3;
    const int g8 = lane >> 3, lr = lane & 7;
    const int wm = wid & 3, wn = wid >> 2;
    const int bl = blockIdx.y, b = bl / L_;
    const int n0 = blockIdx.x * 128;

    const uint32_t aoffA = (uint32_t)((wm * 32 + (g8 & 1) * 8 + lr) * 80 + (g8 >> 1) * 16);
    const uint32_t aoffB = (uint32_t)((wn * 64 + lr) * 80 + g8 * 16);

    if (tid < 128) { biasS[tid] = fb2[n0 + tid]; xacc[tid] = 0.f; }

    const __half* Bbase = g_fw2T + (size_t)n0 * F_;

    for (int mt = 0; mt < 3; ++mt) {
        float acc[2][8][4];
#pragma unroll
        for (int m2 = 0; m2 < 2; ++m2)
#pragma unroll
            for (int nt = 0; nt < 8; ++nt)
#pragma unroll
                for (int j = 0; j < 4; ++j) acc[m2][nt][j] = 0.f;

        const __half* Abase = g_T1h + (size_t)(bl * L_ + mt * 128) * F_;

        stage_async_h(Abase, F_, sb + O_A, tid);
        stage_async_h(Bbase, F_, sb + O_B, tid);
        CP_COMMIT();

        for (int kc = 0; kc < 12; ++kc) {
            const int cur = kc & 1;
            if (kc + 1 < 12) {
                stage_async_h(Abase + (kc + 1) * 32, F_, sb + O_A + (1 - cur) * SB_, tid);
                stage_async_h(Bbase + (kc + 1) * 32, F_, sb + O_B + (1 - cur) * SB_, tid);
                CP_COMMIT();
                CP_WAIT1();
            } else {
                CP_WAIT0();
            }
            __syncthreads();
            mma_chunk(sb + O_A + cur * SB_, sb + O_B + cur * SB_, acc, aoffA, aoffB);
            __syncthreads();
        }

        // Fused epilogue: gelu + bias, * hV, reduce over the 128 k-edge rows
        float p0[8], p1[8];
#pragma unroll
        for (int nt = 0; nt < 8; ++nt) { p0[nt] = 0.f; p1[nt] = 0.f; }

#pragma unroll
        for (int m2 = 0; m2 < 2; ++m2)
#pragma unroll
            for (int nt = 0; nt < 8; ++nt) {
                float* c = acc[m2][nt];
                int r0 = wm * 32 + m2 * 16 + gid;
                int lc = wn * 64 + nt * 8 + 2 * tig;
                float b0v = biasS[lc], b1v = biasS[lc + 1];
                const float* hv0 = hV + ((size_t)b * L_ + mt * 128 + r0) * F_ + n0 + lc;
                float2 h0 = *reinterpret_cast<const float2*>(hv0);
                float2 h1 = *reinterpret_cast<const float2*>(hv0 + (size_t)8 * F_);
                p0[nt] += gelu_f(c[0] + b0v) * h0.x + gelu_f(c[2] + b0v) * h1.x;
                p1[nt] += gelu_f(c[1] + b1v) * h0.y + gelu_f(c[3] + b1v) * h1.y;
            }

        // butterfly over gid (lanes differ in bits 2..4)
#pragma unroll
        for (int nt = 0; nt < 8; ++nt) {
#pragma unroll
            for (int off = 16; off >= 4; off >>= 1) {
                p0[nt] += __shfl_xor_sync(0xFFFFFFFFu, p0[nt], off);
                p1[nt] += __shfl_xor_sync(0xFFFFFFFFu, p1[nt], off);
            }
        }
        if (gid == 0) {
#pragma unroll
            for (int nt = 0; nt < 8; ++nt) {
                red[wm][wn * 64 + nt * 8 + 2 * tig]     = p0[nt];
                red[wm][wn * 64 + nt * 8 + 2 * tig + 1] = p1[nt];
            }
        }
        __syncthreads();
        if (tid < 128)
            xacc[tid] += red[0][tid] + red[1][tid] + red[2][tid] + red[3][tid];
        __syncthreads();
    }

    if (tid < 128) g_xconv[(size_t)bl * F_ + n0 + tid] = xacc[tid];
}

// ---------------------------------------------------------------------------
// Kernel 3: head MLP per (b,l): 384->128 gelu ->64 gelu ->1 ; pred * mask
// ---------------------------------------------------------------------------
__global__ void __launch_bounds__(128) head_kernel(
    const float* __restrict__ hw1, const float* __restrict__ hb1,
    const float* __restrict__ hw2, const float* __restrict__ hb2,
    const float* __restrict__ hw3, const float* __restrict__ hb3,
    const float* __restrict__ mask) {
    const int bl = blockIdx.x;
    const int tid = threadIdx.x;
    __shared__ float xs[F_];
    __shared__ float h1[H_];
    __shared__ float h2[H_ / 2];

    for (int i = tid; i < F_; i += 128) xs[i] = g_xconv[(size_t)bl * F_ + i];
    __syncthreads();

    float s = hb1[tid];
    for (int f = 0; f < F_; ++f) s += xs[f] * hw1[f * H_ + tid];
    h1[tid] = gelu_f(s);
    __syncthreads();

    if (tid < 64) {
        float s2 = hb2[tid];
#pragma unroll 4
        for (int h = 0; h < H_; ++h) s2 += h1[h] * hw2[h * 64 + tid];
        h2[tid] = gelu_f(s2);
    }
    __syncthreads();

    if (tid == 0) {
        float p = hb3[0];
        for (int j = 0; j < 64; ++j) p += h2[j] * hw3[j];
        g_predm[bl] = p * mask[bl];
    }
}

// ---------------------------------------------------------------------------
// Kernel 4: per-batch masked reduction
// ---------------------------------------------------------------------------
__global__ void __launch_bounds__(128) reduce_kernel(const float* __restrict__ mask,
                                                     float* __restrict__ out) {
    const int b = blockIdx.x;
    const int tid = threadIdx.x;
    __shared__ float sp[128];
    __shared__ float smk[128];

    float p = 0.f, mk = 0.f;
    for (int l = tid; l < L_; l += 128) {
        p += g_predm[b * L_ + l];
        mk += mask[b * L_ + l];
    }
    sp[tid] = p; smk[tid] = mk;
    __syncthreads();
    for (int s = 64; s > 0; s >>= 1) {
        if (tid < s) { sp[tid] += sp[tid + s]; smk[tid] += smk[tid + s]; }
        __syncthreads();
    }
    if (tid == 0) {
        float vl = smk[0] < 1.f ? 1.f : smk[0];
        out[b] = sp[0] / sqrtf(vl);
    }
}

// ---------------------------------------------------------------------------
// Launch
// ---------------------------------------------------------------------------
extern "C" void kernel_launch(void* const* d_in, const int* in_sizes, int n_in,
                              void* d_out, int out_size) {
    const float* h_V  = (const float*)d_in[0];
    const float* h_E  = (const float*)d_in[1];
    const float* mask = (const float*)d_in[2];
    const float* fw1  = (const float*)d_in[3];
    const float* fb1  = (const float*)d_in[4];
    const float* fw2  = (const float*)d_in[5];
    const float* fb2  = (const float*)d_in[6];
    const float* hw1  = (const float*)d_in[7];
    const float* hb1  = (const float*)d_in[8];
    const float* hw2  = (const float*)d_in[9];
    const float* hb2  = (const float*)d_in[10];
    const float* hw3  = (const float*)d_in[11];
    const float* hb3  = (const float*)d_in[12];
    float* out = (float*)d_out;

    static int configured = 0;
    if (!configured) {
        cudaFuncSetAttribute(gemm1_mma, cudaFuncAttributeMaxDynamicSharedMemorySize, SMEM1);
        cudaFuncSetAttribute(gemm2_mma, cudaFuncAttributeMaxDynamicSharedMemorySize, SMEM2);
        configured = 1;
    }

    conv_hE<<<((size_t)M1_ * H_) / (256 * 4), 256>>>(h_E);
    transpose_w<<<(F_ * H_ + F_ * F_ + 255) / 256, 256>>>(fw1, fw2);

    dim3 g1(F_ / 128, M1_ / 128);            // (3, 4608)
    gemm1_mma<<<g1, 256, SMEM1>>>(fb1);

    dim3 g2(F_ / 128, B_ * L_);              // (3, 1536)
    gemm2_mma<<<g2, 256, SMEM2>>>(h_V, fb2);

    head_kernel<<<B_ * L_, 128>>>(hw1, hb1, hw2, hb2, hw3, hb3, mask);
    reduce_kernel<<<B_, 128>>>(mask, out);
}